// round 1
// baseline (speedup 1.0000x reference)
#include <cuda_runtime.h>

#define B  32
#define D  768
#define H  3072
#define T  8
#define MH 192

// ---------------- scratch (device globals; no allocation allowed) ----------
__device__ float g_m  [B*D];        // patch mean per sample
__device__ float g_f0 [B*D];        // m@Wp + bp
__device__ float g_Ap [B*T*D];      // m@dWp[t]
__device__ float g_z  [B*H];        // f0@W1 + b1 (pre-relu)
__device__ float g_f  [B*H];        // relu(z)
__device__ float g_Z1 [B*T*H];      // f0@dW1[t]
__device__ float g_base[B*D];       // f@W2 + b2
__device__ float g_F2 [B*T*D];      // f@dW2[t]
__device__ float g_coef[B*T*6];     // metanet coefficients
__device__ float g_df0[B*D];
__device__ float g_dzp[B*H];        // sum_t c2*Z1 + c3*db1
__device__ float g_df [B*H];        // relu'(z)*dz

// ---------------- packed f32x2 helpers -------------------------------------
__device__ __forceinline__ void ffma2(unsigned long long &d,
                                      unsigned long long a,
                                      unsigned long long b) {
#if __CUDA_ARCH__ >= 1000
    asm("fma.rn.f32x2 %0, %1, %2, %0;" : "+l"(d) : "l"(a), "l"(b));
#else
    float alo, ahi, blo, bhi, dlo, dhi;
    asm("mov.b64 {%0,%1}, %2;" : "=f"(alo), "=f"(ahi) : "l"(a));
    asm("mov.b64 {%0,%1}, %2;" : "=f"(blo), "=f"(bhi) : "l"(b));
    asm("mov.b64 {%0,%1}, %2;" : "=f"(dlo), "=f"(dhi) : "l"(d));
    dlo = fmaf(alo, blo, dlo); dhi = fmaf(ahi, bhi, dhi);
    asm("mov.b64 %0, {%1,%2};" : "=l"(d) : "f"(dlo), "f"(dhi));
#endif
}
__device__ __forceinline__ unsigned long long bcast2(float w) {
    unsigned long long r;
    asm("mov.b64 %0, {%1, %1};" : "=l"(r) : "f"(w));
    return r;
}
__device__ __forceinline__ void unpack2(unsigned long long v, float &lo, float &hi) {
    asm("mov.b64 {%0, %1}, %2;" : "=f"(lo), "=f"(hi) : "l"(v));
}

// ---------------- K1: patch mean (strided avg pool) -------------------------
__global__ void patch_mean_kernel(const float* __restrict__ x) {
    int bc = blockIdx.x;            // 0..95
    int b = bc / 3, c = bc % 3;
    int tid = threadIdx.x;          // 256
    int dy = tid >> 4, dx = tid & 15;
    const float* base = x + (((size_t)b * 3 + c) * 224 + dy) * 224 + dx;
    float s = 0.f;
    #pragma unroll
    for (int py = 0; py < 14; py++) {
        const float* r = base + py * 16 * 224;
        #pragma unroll
        for (int px = 0; px < 14; px++) s += r[px * 16];
    }
    g_m[b * D + c * 256 + dy * 16 + dx] = s * (1.0f / 196.0f);
}

// ---------------- init base/F2 (bias preload + zero for atomic k-split) ----
__global__ void init_baseF2_kernel(const float* __restrict__ b2) {
    int n = blockIdx.x * 256 + threadIdx.x;
    if (n < B * D) g_base[n] = b2[n % D];
    for (int i = n; i < B * T * D; i += gridDim.x * 256) g_F2[i] = 0.f;
}

// ---------------- generic skinny GEMM --------------------------------------
// C[b,n] = sum_k A[b,k] * W[k,n], A:[32,KTOT], weights streamed.
// MODE: 0=K2(m->f0/Ap)  1=K3(f0->z,f/Z1)  2=K4(f->base/F2, atomic)
//       3=K7(df0@W1 -> df, w/ relu mask)  4=K8(df@W2 -> atomicAdd dst)
template<int KTOT, int NC, int NSPLIT, int MODE>
__global__ void __launch_bounds__(256, 2) gemm_skinny(
    const float* __restrict__ W0,
    const float* __restrict__ Wd,
    const float* __restrict__ bias,
    float* __restrict__ dst)
{
    __shared__ unsigned long long sred[8 * 16 * 32];   // 32KB, aliased w/ A staging
    float* sA = (float*)sred;                          // [8 warps][32 k][32 b]

    const float* A;
    if      (MODE == 0) A = g_m;
    else if (MODE == 1) A = g_f0;
    else if (MODE == 2) A = g_f;
    else if (MODE == 3) A = g_df0;
    else                A = g_df;

    const int tid  = threadIdx.x;
    const int w    = tid >> 5;
    const int lane = tid & 31;
    const int n0   = blockIdx.x * 32;
    const int gt   = n0 / NC;
    const int c0   = n0 % NC;
    const float* wcol = (gt == 0 ? W0 : Wd + (size_t)(gt - 1) * KTOT * NC) + c0 + lane;

    constexpr int KC = KTOT / (8 * NSPLIT);
    const int kbeg = (blockIdx.y * 8 + w) * KC;

    unsigned long long acc[16];
    #pragma unroll
    for (int i = 0; i < 16; i++) acc[i] = 0ULL;

    float* sAw = sA + w * 32 * 32;

    for (int kc = 0; kc < KC; kc += 32) {
        const int kb = kbeg + kc;
        // stage A[lane][kb..kb+31] transposed into sAw[k][b]
        const float4* arow = (const float4*)(A + (size_t)lane * KTOT + kb);
        #pragma unroll
        for (int i = 0; i < 8; i++) {
            float4 v = arow[i];
            sAw[(4 * i + 0) * 32 + lane] = v.x;
            sAw[(4 * i + 1) * 32 + lane] = v.y;
            sAw[(4 * i + 2) * 32 + lane] = v.z;
            sAw[(4 * i + 3) * 32 + lane] = v.w;
        }
        __syncwarp();
        const float* wp = wcol + (size_t)kb * NC;
        #pragma unroll
        for (int q = 0; q < 4; q++) {
            float wbuf[8];
            #pragma unroll
            for (int j = 0; j < 8; j++) wbuf[j] = wp[(size_t)(q * 8 + j) * NC];
            #pragma unroll
            for (int j = 0; j < 8; j++) {
                unsigned long long w2 = bcast2(wbuf[j]);
                const ulonglong2* ar = (const ulonglong2*)(sAw + (q * 8 + j) * 32);
                #pragma unroll
                for (int i = 0; i < 8; i++) {
                    ulonglong2 v = ar[i];
                    ffma2(acc[2 * i + 0], v.x, w2);
                    ffma2(acc[2 * i + 1], v.y, w2);
                }
            }
        }
        __syncwarp();
    }

    // each warp dumps partials into its own 4KB slice (same region it staged A in)
    #pragma unroll
    for (int i = 0; i < 16; i++) sred[(w * 16 + i) * 32 + lane] = acc[i];
    __syncthreads();

    // cross-warp reduce: 512 (b-pair, col) items over 256 threads
    #pragma unroll
    for (int r = tid; r < 512; r += 256) {
        const int i = r >> 5;        // b-pair 0..15
        const int col = r & 31;
        float lo = 0.f, hi = 0.f;
        #pragma unroll
        for (int ww = 0; ww < 8; ww++) {
            float a, b;
            unpack2(sred[(ww * 16 + i) * 32 + col], a, b);
            lo += a; hi += b;
        }
        const int b0 = 2 * i, b1 = 2 * i + 1;
        const int c = c0 + col;
        if constexpr (MODE == 0) {
            if (gt == 0) {
                float bv = bias[c];
                g_f0[b0 * NC + c] = lo + bv;
                g_f0[b1 * NC + c] = hi + bv;
            } else {
                int t = gt - 1;
                g_Ap[((size_t)b0 * T + t) * NC + c] = lo;
                g_Ap[((size_t)b1 * T + t) * NC + c] = hi;
            }
        } else if constexpr (MODE == 1) {
            if (gt == 0) {
                float bv = bias[c];
                float z0 = lo + bv, z1 = hi + bv;
                g_z[b0 * NC + c] = z0;              g_z[b1 * NC + c] = z1;
                g_f[b0 * NC + c] = fmaxf(z0, 0.f);  g_f[b1 * NC + c] = fmaxf(z1, 0.f);
            } else {
                int t = gt - 1;
                g_Z1[((size_t)b0 * T + t) * NC + c] = lo;
                g_Z1[((size_t)b1 * T + t) * NC + c] = hi;
            }
        } else if constexpr (MODE == 2) {
            if (gt == 0) {
                atomicAdd(&g_base[b0 * NC + c], lo);
                atomicAdd(&g_base[b1 * NC + c], hi);
            } else {
                int t = gt - 1;
                atomicAdd(&g_F2[((size_t)b0 * T + t) * NC + c], lo);
                atomicAdd(&g_F2[((size_t)b1 * T + t) * NC + c], hi);
            }
        } else if constexpr (MODE == 3) {
            float z0 = g_z[b0 * NC + c];
            float z1 = g_z[b1 * NC + c];
            g_df[b0 * NC + c] = (z0 > 0.f) ? (lo + g_dzp[b0 * NC + c]) : 0.f;
            g_df[b1 * NC + c] = (z1 > 0.f) ? (hi + g_dzp[b1 * NC + c]) : 0.f;
        } else {
            atomicAdd(&dst[b0 * NC + c], lo);
            atomicAdd(&dst[b1 * NC + c], hi);
        }
    }
}

// ---------------- K5: metanet (base -> coefs) -------------------------------
__global__ void meta_kernel(const float* __restrict__ mW1, const float* __restrict__ mb1,
                            const float* __restrict__ mW2, const float* __restrict__ mb2)
{
    __shared__ float sb[D];
    __shared__ float sg[MH];
    const int b = blockIdx.x;
    const int tid = threadIdx.x;   // 192
    for (int i = tid; i < D; i += MH) sb[i] = g_base[b * D + i];
    __syncthreads();
    float h = mb1[tid];
    #pragma unroll 8
    for (int k = 0; k < D; k++) h = fmaf(sb[k], mW1[k * MH + tid], h);
    sg[tid] = fmaxf(h, 0.f);
    __syncthreads();
    if (tid < T * 6) {
        float cc = mb2[tid];
        #pragma unroll 8
        for (int k = 0; k < MH; k++) cc = fmaf(sg[k], mW2[k * (T * 6) + tid], cc);
        g_coef[b * (T * 6) + tid] = cc;
    }
}

// ---------------- K6: coefficient contraction + output init -----------------
__global__ void combine_kernel(const float* __restrict__ dbp,
                               const float* __restrict__ db1,
                               const float* __restrict__ db2,
                               float* __restrict__ dst)
{
    __shared__ float sc[T * 6];
    const int b = blockIdx.x;
    const int tid = threadIdx.x;
    if (tid < T * 6) sc[tid] = g_coef[b * (T * 6) + tid];
    __syncthreads();
    const int n = blockIdx.y * 256 + tid;
    if (n < D) {
        float s = 0.f;
        #pragma unroll
        for (int t = 0; t < T; t++)
            s += sc[t * 6 + 0] * g_Ap[((size_t)b * T + t) * D + n]
               + sc[t * 6 + 1] * dbp[t * D + n];
        g_df0[b * D + n] = s;
    } else if (n < D + H) {
        const int j = n - D;
        float s = 0.f;
        #pragma unroll
        for (int t = 0; t < T; t++)
            s += sc[t * 6 + 2] * g_Z1[((size_t)b * T + t) * H + j]
               + sc[t * 6 + 3] * db1[t * H + j];
        g_dzp[b * H + j] = s;
    } else {
        const int j = n - D - H;
        float s = g_base[b * D + j];
        #pragma unroll
        for (int t = 0; t < T; t++)
            s += sc[t * 6 + 4] * g_F2[((size_t)b * T + t) * D + j]
               + sc[t * 6 + 5] * db2[t * D + j];
        dst[b * D + j] = s;
    }
}

// ---------------- launch ----------------------------------------------------
extern "C" void kernel_launch(void* const* d_in, const int* in_sizes, int n_in,
                              void* d_out, int out_size)
{
    const float* x   = (const float*)d_in[0];
    const float* Wp  = (const float*)d_in[1];
    const float* bp  = (const float*)d_in[2];
    const float* W1  = (const float*)d_in[3];
    const float* b1  = (const float*)d_in[4];
    const float* W2  = (const float*)d_in[5];
    const float* b2  = (const float*)d_in[6];
    const float* dWp = (const float*)d_in[7];
    const float* dbp = (const float*)d_in[8];
    const float* dW1 = (const float*)d_in[9];
    const float* db1 = (const float*)d_in[10];
    const float* dW2 = (const float*)d_in[11];
    const float* db2 = (const float*)d_in[12];
    const float* mW1 = (const float*)d_in[13];
    const float* mb1 = (const float*)d_in[14];
    const float* mW2 = (const float*)d_in[15];
    const float* mb2 = (const float*)d_in[16];
    float* out = (float*)d_out;

    // K1: patch means
    patch_mean_kernel<<<96, 256>>>(x);
    // K2: f0 = m@Wp+bp ; Ap[t] = m@dWp[t]   N = 9*768
    gemm_skinny<768, 768, 1, 0><<<dim3(9 * D / 32, 1), 256>>>(Wp, dWp, bp, nullptr);
    // init base/F2 (bias preload for atomic k-split of K4)
    init_baseF2_kernel<<<96, 256>>>(b2);
    // K3: z,f = f0@W1+b1 ; Z1[t] = f0@dW1[t]  N = 9*3072
    gemm_skinny<768, 3072, 1, 1><<<dim3(9 * H / 32, 1), 256>>>(W1, dW1, b1, nullptr);
    // K4: base = f@W2+b2 ; F2[t] = f@dW2[t]   N = 9*768, k-split 2
    gemm_skinny<3072, 768, 2, 2><<<dim3(9 * D / 32, 2), 256>>>(W2, dW2, nullptr, nullptr);
    // K5: metanet coefficients
    meta_kernel<<<B, MH>>>(mW1, mb1, mW2, mb2);
    // K6: df0, dzp, out-init = base + sum c4*F2 + c5*db2
    combine_kernel<<<dim3(B, (D + H + D) / 256), 256>>>(dbp, db1, db2, out);
    // K7: df = (z>0) * (df0@W1 + dzp)
    gemm_skinny<768, 3072, 1, 3><<<dim3(H / 32, 1), 256>>>(W1, nullptr, nullptr, nullptr);
    // K8: out += df@W2   (k-split 6, atomic)
    gemm_skinny<3072, 768, 6, 4><<<dim3(D / 32, 6), 256>>>(W2, nullptr, nullptr, out);
}

// round 2
// speedup vs baseline: 1.0972x; 1.0972x over previous
#include <cuda_runtime.h>

#define B  32
#define D  768
#define H  3072
#define T  8
#define MH 192

typedef unsigned long long ull;

// ---------------- scratch (device globals; no allocation allowed) ----------
__device__ float g_m  [B*D];        // patch mean per sample
__device__ float g_f0 [B*D];        // m@Wp + bp
__device__ float g_Ap [B*T*D];      // m@dWp[t]
__device__ float g_z  [B*H];        // f0@W1 + b1 (pre-relu)
__device__ float g_f  [B*H];        // relu(z)
__device__ float g_Z1 [B*T*H];      // f0@dW1[t]
__device__ float g_base[B*D];       // f@W2 + b2
__device__ float g_F2 [B*T*D];      // f@dW2[t]
__device__ float g_coef[B*T*6];     // metanet coefficients
__device__ float g_df0[B*D];
__device__ float g_dzp[B*H];        // sum_t c2*Z1 + c3*db1  (+= df0@W1 via K7)
__device__ float g_df [B*H];        // relu'(z)*dz

// ---------------- packed f32x2 helpers -------------------------------------
__device__ __forceinline__ void ffma2(ull &d, ull a, ull b) {
    asm("fma.rn.f32x2 %0, %1, %2, %0;" : "+l"(d) : "l"(a), "l"(b));
}
__device__ __forceinline__ ull bcast2(float w) {
    ull r;
    asm("mov.b64 %0, {%1, %1};" : "=l"(r) : "f"(w));
    return r;
}
__device__ __forceinline__ void unpack2(ull v, float &lo, float &hi) {
    asm("mov.b64 {%0, %1}, %2;" : "=f"(lo), "=f"(hi) : "l"(v));
}
__device__ __forceinline__ ull addp(ull a, ull b) {
    ull r;
    asm("add.rn.f32x2 %0, %1, %2;" : "=l"(r) : "l"(a), "l"(b));
    return r;
}

// ---------------- K1: patch mean (strided avg pool) -------------------------
__global__ void patch_mean_kernel(const float* __restrict__ x) {
    int bc = blockIdx.x;            // 0..95
    int b = bc / 3, c = bc % 3;
    int tid = threadIdx.x;          // 256
    int dy = tid >> 4, dx = tid & 15;
    const float* base = x + (((size_t)b * 3 + c) * 224 + dy) * 224 + dx;
    float s = 0.f;
    #pragma unroll
    for (int py = 0; py < 14; py++) {
        const float* r = base + py * 16 * 224;
        #pragma unroll
        for (int px = 0; px < 14; px++) s += r[px * 16];
    }
    g_m[b * D + c * 256 + dy * 16 + dx] = s * (1.0f / 196.0f);
}

// ---------------- init: bias preload + zeros for atomic k-split ------------
__global__ void init_kernel(const float* __restrict__ bp,
                            const float* __restrict__ b1,
                            const float* __restrict__ b2) {
    int i = blockIdx.x * 256 + threadIdx.x;      // grid 384 -> covers B*H
    if (i < B * D) { g_f0[i] = bp[i % D]; g_base[i] = b2[i % D]; }
    if (i < B * H) g_z[i] = b1[i % H];
    for (int j = i; j < B * T * D; j += gridDim.x * 256) { g_Ap[j] = 0.f; g_F2[j] = 0.f; }
    for (int j = i; j < B * T * H; j += gridDim.x * 256) g_Z1[j] = 0.f;
}

__global__ void relu_kernel() {
    int i = blockIdx.x * 256 + threadIdx.x;
    if (i < B * H) g_f[i] = fmaxf(g_z[i], 0.f);
}

__global__ void mask_kernel() {
    int i = blockIdx.x * 256 + threadIdx.x;
    if (i < B * H) g_df[i] = (g_z[i] > 0.f) ? g_dzp[i] : 0.f;
}

// ---------------- skinny GEMM v2: 4 cols/thread, 128 cols/block -------------
// C[b,n] += sum_k A[b,k] * W[k,n]  (atomic accumulate, k-split over grid.y x 4 warpsegs)
// warp w: kseg = w>>1 (0..3), bhalf = w&1 (batch rows bh*16..bh*16+15)
// thread lane: cols c0 + 4*lane + {0..3}; acc[c][p] over 8 batch-pairs.
// MODE: 0: ->g_f0/g_Ap   1: ->g_z/g_Z1   2: ->g_base/g_F2
//       3: ->g_dzp (A=g_df0)             4: ->dst (A=g_df)
template<int KTOT, int NC, int MODE>
__global__ void __launch_bounds__(256, 2) gemm2(
    const float* __restrict__ W0,
    const float* __restrict__ Wd,
    float* __restrict__ dst)
{
    __shared__ float sA[8][16 * 16];   // per-warp staging [k][b] (8KB)
    __shared__ ull  sred[2048];        // reduction (16KB)

    const int tid  = threadIdx.x;
    const int w    = tid >> 5;
    const int lane = tid & 31;
    const int kseg = w >> 1;
    const int bh   = w & 1;

    const float* A;
    if      (MODE == 0) A = g_m;
    else if (MODE == 1) A = g_f0;
    else if (MODE == 2) A = g_f;
    else if (MODE == 3) A = g_df0;
    else                A = g_df;

    const int n0 = blockIdx.x * 128;
    const int gt = n0 / NC;
    const int c0 = n0 % NC;
    const float* wp = (gt == 0 ? W0 : Wd + (size_t)(gt - 1) * KTOT * NC) + c0 + 4 * lane;

    const int Y   = gridDim.y;
    const int KC  = KTOT / (4 * Y);                 // multiple of 16 by construction
    const int kbeg = (blockIdx.y * 4 + kseg) * KC;

    const int rr = lane & 15, kh = lane >> 4;       // staging roles
    const float* aptr = A + (size_t)(bh * 16 + rr) * KTOT + kbeg + kh * 8;

    ull acc[32];
    #pragma unroll
    for (int i = 0; i < 32; i++) acc[i] = 0ULL;

    float* sAw = sA[w];

    for (int kc = 0; kc < KC; kc += 16) {
        // stage 16k x 16b transposed (warp-private)
        float4 v0 = *(const float4*)(aptr + kc);
        float4 v1 = *(const float4*)(aptr + kc + 4);
        __syncwarp();
        sAw[(kh * 8 + 0) * 16 + rr] = v0.x;
        sAw[(kh * 8 + 1) * 16 + rr] = v0.y;
        sAw[(kh * 8 + 2) * 16 + rr] = v0.z;
        sAw[(kh * 8 + 3) * 16 + rr] = v0.w;
        sAw[(kh * 8 + 4) * 16 + rr] = v1.x;
        sAw[(kh * 8 + 5) * 16 + rr] = v1.y;
        sAw[(kh * 8 + 6) * 16 + rr] = v1.z;
        sAw[(kh * 8 + 7) * 16 + rr] = v1.w;
        __syncwarp();

        const float* wrow = wp + (size_t)(kbeg + kc) * NC;
        #pragma unroll 4
        for (int k = 0; k < 16; k++) {
            float4 wv = *(const float4*)wrow;
            wrow += NC;
            const ulonglong2* ar = (const ulonglong2*)(sAw + k * 16);
            ulonglong2 q0 = ar[0], q1 = ar[1], q2 = ar[2], q3 = ar[3];
            ull aa[8] = {q0.x, q0.y, q1.x, q1.y, q2.x, q2.y, q3.x, q3.y};
            ull wc[4] = {bcast2(wv.x), bcast2(wv.y), bcast2(wv.z), bcast2(wv.w)};
            #pragma unroll
            for (int c = 0; c < 4; c++)
                #pragma unroll
                for (int p = 0; p < 8; p++)
                    ffma2(acc[c * 8 + p], aa[p], wc[c]);
        }
    }

    // cross-kseg reduction: 4 sequential rounds into sred[(c*8+p)*64 + bh*32+lane]
    if (kseg == 0) {
        #pragma unroll
        for (int i = 0; i < 32; i++) sred[i * 64 + bh * 32 + lane] = acc[i];
    }
    __syncthreads();
    #pragma unroll
    for (int r = 1; r < 4; r++) {
        if (kseg == r) {
            #pragma unroll
            for (int i = 0; i < 32; i++) {
                int idx = i * 64 + bh * 32 + lane;
                sred[idx] = addp(sred[idx], acc[i]);
            }
        }
        __syncthreads();
    }

    // all 256 threads flush 8 packed pairs each -> atomics
    #pragma unroll
    for (int i = 0; i < 8; i++) {
        const int L    = tid * 8 + i;
        const int pos  = L & 63;
        const int slot = L >> 6;
        const int c    = slot >> 3, p = slot & 7;
        const int bhh  = pos >> 5,  ln = pos & 31;
        const int col  = c0 + 4 * ln + c;
        const int b0   = bhh * 16 + 2 * p;
        float lo, hi;
        unpack2(sred[L], lo, hi);
        if constexpr (MODE == 0) {
            if (gt == 0) {
                atomicAdd(&g_f0[b0 * D + col], lo);
                atomicAdd(&g_f0[(b0 + 1) * D + col], hi);
            } else {
                atomicAdd(&g_Ap[((size_t)b0 * T + gt - 1) * D + col], lo);
                atomicAdd(&g_Ap[((size_t)(b0 + 1) * T + gt - 1) * D + col], hi);
            }
        } else if constexpr (MODE == 1) {
            if (gt == 0) {
                atomicAdd(&g_z[b0 * H + col], lo);
                atomicAdd(&g_z[(b0 + 1) * H + col], hi);
            } else {
                atomicAdd(&g_Z1[((size_t)b0 * T + gt - 1) * H + col], lo);
                atomicAdd(&g_Z1[((size_t)(b0 + 1) * T + gt - 1) * H + col], hi);
            }
        } else if constexpr (MODE == 2) {
            if (gt == 0) {
                atomicAdd(&g_base[b0 * D + col], lo);
                atomicAdd(&g_base[(b0 + 1) * D + col], hi);
            } else {
                atomicAdd(&g_F2[((size_t)b0 * T + gt - 1) * D + col], lo);
                atomicAdd(&g_F2[((size_t)(b0 + 1) * T + gt - 1) * D + col], hi);
            }
        } else if constexpr (MODE == 3) {
            atomicAdd(&g_dzp[b0 * H + col], lo);
            atomicAdd(&g_dzp[(b0 + 1) * H + col], hi);
        } else {
            atomicAdd(&dst[b0 * D + col], lo);
            atomicAdd(&dst[(b0 + 1) * D + col], hi);
        }
    }
}

// ---------------- K5: metanet (base -> coefs) -------------------------------
__global__ void meta_kernel(const float* __restrict__ mW1, const float* __restrict__ mb1,
                            const float* __restrict__ mW2, const float* __restrict__ mb2)
{
    __shared__ float sb[D];
    __shared__ float sg[MH];
    const int b = blockIdx.x;
    const int tid = threadIdx.x;   // 192
    for (int i = tid; i < D; i += MH) sb[i] = g_base[b * D + i];
    __syncthreads();
    float h = mb1[tid];
    #pragma unroll 8
    for (int k = 0; k < D; k++) h = fmaf(sb[k], mW1[k * MH + tid], h);
    sg[tid] = fmaxf(h, 0.f);
    __syncthreads();
    if (tid < T * 6) {
        float cc = mb2[tid];
        #pragma unroll 8
        for (int k = 0; k < MH; k++) cc = fmaf(sg[k], mW2[k * (T * 6) + tid], cc);
        g_coef[b * (T * 6) + tid] = cc;
    }
}

// ---------------- K6: coefficient contraction + output init -----------------
__global__ void combine_kernel(const float* __restrict__ dbp,
                               const float* __restrict__ db1,
                               const float* __restrict__ db2,
                               float* __restrict__ dst)
{
    __shared__ float sc[T * 6];
    const int b = blockIdx.x;
    const int tid = threadIdx.x;
    if (tid < T * 6) sc[tid] = g_coef[b * (T * 6) + tid];
    __syncthreads();
    const int n = blockIdx.y * 256 + tid;
    if (n < D) {
        float s = 0.f;
        #pragma unroll
        for (int t = 0; t < T; t++)
            s += sc[t * 6 + 0] * g_Ap[((size_t)b * T + t) * D + n]
               + sc[t * 6 + 1] * dbp[t * D + n];
        g_df0[b * D + n] = s;
    } else if (n < D + H) {
        const int j = n - D;
        float s = 0.f;
        #pragma unroll
        for (int t = 0; t < T; t++)
            s += sc[t * 6 + 2] * g_Z1[((size_t)b * T + t) * H + j]
               + sc[t * 6 + 3] * db1[t * H + j];
        g_dzp[b * H + j] = s;
    } else {
        const int j = n - D - H;
        float s = g_base[b * D + j];
        #pragma unroll
        for (int t = 0; t < T; t++)
            s += sc[t * 6 + 4] * g_F2[((size_t)b * T + t) * D + j]
               + sc[t * 6 + 5] * db2[t * D + j];
        dst[b * D + j] = s;
    }
}

// ---------------- launch ----------------------------------------------------
extern "C" void kernel_launch(void* const* d_in, const int* in_sizes, int n_in,
                              void* d_out, int out_size)
{
    const float* x   = (const float*)d_in[0];
    const float* Wp  = (const float*)d_in[1];
    const float* bp  = (const float*)d_in[2];
    const float* W1  = (const float*)d_in[3];
    const float* b1  = (const float*)d_in[4];
    const float* W2  = (const float*)d_in[5];
    const float* b2  = (const float*)d_in[6];
    const float* dWp = (const float*)d_in[7];
    const float* dbp = (const float*)d_in[8];
    const float* dW1 = (const float*)d_in[9];
    const float* db1 = (const float*)d_in[10];
    const float* dW2 = (const float*)d_in[11];
    const float* db2 = (const float*)d_in[12];
    const float* mW1 = (const float*)d_in[13];
    const float* mb1 = (const float*)d_in[14];
    const float* mW2 = (const float*)d_in[15];
    const float* mb2 = (const float*)d_in[16];
    float* out = (float*)d_out;

    patch_mean_kernel<<<96, 256>>>(x);
    init_kernel<<<384, 256>>>(bp, b1, b2);
    // K2: f0 / Ap  N=9*768,  KTOT=768,  Y=4  -> 216 blocks, KC=48
    gemm2<768, 768, 0><<<dim3(54, 4), 256>>>(Wp, dWp, nullptr);
    // K3: z / Z1   N=9*3072, KTOT=768,  Y=2  -> 432 blocks, KC=96
    gemm2<768, 3072, 1><<<dim3(216, 2), 256>>>(W1, dW1, nullptr);
    relu_kernel<<<384, 256>>>();
    // K4: base/F2  N=9*768,  KTOT=3072, Y=8  -> 432 blocks, KC=96
    gemm2<3072, 768, 2><<<dim3(54, 8), 256>>>(W2, dW2, nullptr);
    meta_kernel<<<B, MH>>>(mW1, mb1, mW2, mb2);
    combine_kernel<<<dim3(B, 18), 256>>>(dbp, db1, db2, out);
    // K7: dzp += df0@W1   N=3072, KTOT=768,  Y=4 -> 96 blocks, KC=48
    gemm2<768, 3072, 3><<<dim3(24, 4), 256>>>(W1, nullptr, nullptr);
    mask_kernel<<<384, 256>>>();
    // K8: out += df@W2    N=768,  KTOT=3072, Y=16 -> 96 blocks, KC=48
    gemm2<3072, 768, 4><<<dim3(6, 16), 256>>>(W2, nullptr, out);
}